// round 13
// baseline (speedup 1.0000x reference)
#include <cuda_runtime.h>
#include <cuda_fp16.h>
#include <cstdint>
#include <math.h>

// ---------------- problem constants ----------------
constexpr int BN  = 4;
constexpr int SN  = 2048;
constexpr int DN  = 2048;
constexpr int HN  = 16;
constexpr int DHN = 128;
constexpr int BH  = BN * HN;      // 64
constexpr int MR  = BN * SN;      // 8192
constexpr float QK_SCALE = 0.08838834764831845f;
constexpr float LOG2E    = 1.4426950408889634f;

// ---------------- static device scratch ----------------
__device__ __half g_qkvh[3][(size_t)MR * DN];     // fp16 q,k,v
__device__ __half g_Wt  [4][(size_t)DN * DN];     // transposed fp16 Wq,Wk,Wv,Wo
__device__ __half g_Q  [(size_t)BH * SN * DHN];   // [bh,s,dh] fp16 (pre-scaled, log2 domain)
__device__ __half g_K  [(size_t)BH * SN * DHN];   // [bh,s,dh]
__device__ __half g_Vh [(size_t)BH * SN * DHN];   // [bh,s,dh] (flash uses ldmatrix.trans)
__device__ __half g_Vm [(size_t)MR * DN];         // merged V proj [B,S,D]
__device__ __half g_PVm[(size_t)MR * DN];         // merged PV [B,S,D]
__device__ float  g_U  [(size_t)MR * DN];         // Vm @ Wo
__device__ float  g_SUF[(size_t)MR * DN];         // suffix sums of U
__device__ float  g_SEG[(size_t)BN * 16 * DN];

// ---------------- helpers ----------------
__device__ __forceinline__ uint32_t smem_u32(const void* p) {
    uint32_t a;
    asm("{ .reg .u64 t; cvta.to.shared.u64 t, %1; cvt.u32.u64 %0, t; }" : "=r"(a) : "l"(p));
    return a;
}
__device__ __forceinline__ float ex2f(float x) {
    float y;
    asm("ex2.approx.ftz.f32 %0, %1;" : "=f"(y) : "f"(x));
    return y;
}
__device__ __forceinline__ void cp_async16(uint32_t dst, const void* src) {
    asm volatile("cp.async.cg.shared.global [%0], [%1], 16;" :: "r"(dst), "l"(src));
}
__device__ __forceinline__ void cp_commit() { asm volatile("cp.async.commit_group;"); }
__device__ __forceinline__ void cp_wait0()  { asm volatile("cp.async.wait_group 0;"); }
__device__ __forceinline__ void cp_wait1()  { asm volatile("cp.async.wait_group 1;"); }
__device__ __forceinline__ uint32_t swz(uint32_t off) {
    return off ^ ((off >> 3) & 0x70);
}
__device__ __forceinline__ void ldsm4(uint32_t& r0, uint32_t& r1, uint32_t& r2, uint32_t& r3,
                                      uint32_t addr) {
    asm volatile("ldmatrix.sync.aligned.m8n8.x4.shared.b16 {%0,%1,%2,%3}, [%4];"
        : "=r"(r0), "=r"(r1), "=r"(r2), "=r"(r3) : "r"(addr));
}
__device__ __forceinline__ void ldsm4t(uint32_t& r0, uint32_t& r1, uint32_t& r2, uint32_t& r3,
                                       uint32_t addr) {
    asm volatile("ldmatrix.sync.aligned.m8n8.x4.trans.shared.b16 {%0,%1,%2,%3}, [%4];"
        : "=r"(r0), "=r"(r1), "=r"(r2), "=r"(r3) : "r"(addr));
}
__device__ __forceinline__ void mma_16816(float* c, const uint32_t* a, const uint32_t* b) {
    asm volatile("mma.sync.aligned.m16n8k16.row.col.f32.f16.f16.f32 "
        "{%0,%1,%2,%3},{%4,%5,%6,%7},{%8,%9},{%0,%1,%2,%3};"
        : "+f"(c[0]), "+f"(c[1]), "+f"(c[2]), "+f"(c[3])
        : "r"(a[0]), "r"(a[1]), "r"(a[2]), "r"(a[3]), "r"(b[0]), "r"(b[1]));
}

// ================= GEMM core (128x128 CTA tile, 3-stage, 2 CTA/SM) =================
constexpr int GM_STAGE = 32768;            // A 16KB + B 16KB
constexpr int GM_SMEM  = 3 * GM_STAGE;     // 96KB

template<typename EpiFn>
__device__ __forceinline__ void gemm_body(
    const __half* __restrict__ A, const __half* __restrict__ Bm,
    int K, int lda, int ldb, uint32_t sb, EpiFn epi)
{
    const int tid = threadIdx.x, wid = tid >> 5, lane = tid & 31;
    const int wm = wid >> 2, wn = wid & 3;           // 2x4 warp grid
    const int m0 = blockIdx.y * 128, n0 = blockIdx.x * 128;

    float acc[64];
#pragma unroll
    for (int i = 0; i < 64; i++) acc[i] = 0.f;

    const int CC = K >> 6;   // 64-half chunks

    auto load_chunk = [&](int st, int c) {
        int k0 = c << 6;
        const uint32_t sa = sb + st * GM_STAGE;
#pragma unroll
        for (int i = 0; i < 4; i++) {
            int u = tid + i * 256;
            int r = u >> 3, ku = u & 7;
            cp_async16(sa + swz(r * 128 + ku * 16),
                       A + (size_t)(m0 + r) * lda + k0 + ku * 8);
        }
#pragma unroll
        for (int i = 0; i < 4; i++) {
            int u = tid + i * 256;
            int r = u >> 3, ku = u & 7;
            cp_async16(sa + 16384 + swz(r * 128 + ku * 16),
                       Bm + (size_t)(n0 + r) * ldb + k0 + ku * 8);
        }
        cp_commit();
    };

    const int row16 = lane & 15;
    const int aKh   = (lane >> 4) & 1;
    uint32_t aBase[4], aSx[4];
#pragma unroll
    for (int mt = 0; mt < 4; mt++) {
        int m = wm * 64 + mt * 16 + row16;
        aBase[mt] = m * 128;
        aSx[mt] = (m & 7) << 4;
    }
    const int bKh   = (lane >> 3) & 1;
    const int bN8   = (lane >> 4) & 1;
    uint32_t bBase[2], bSx[2];
#pragma unroll
    for (int p = 0; p < 2; p++) {
        int n = wn * 32 + p * 16 + bN8 * 8 + (lane & 7);
        bBase[p] = 16384 + n * 128;
        bSx[p] = (n & 7) << 4;
    }

    load_chunk(0, 0);
    load_chunk(1, 1);
    int st = 0;
    for (int c = 0; c < CC; c++) {
        if (c < CC - 1) cp_wait1(); else cp_wait0();
        __syncthreads();
        if (c + 2 < CC) {
            int st2 = st + 2; if (st2 >= 3) st2 -= 3;
            load_chunk(st2, c + 2);
        }
        const uint32_t buf = sb + st * GM_STAGE;
#pragma unroll
        for (int kk = 0; kk < 4; kk++) {
            uint32_t a[4][4];
            const uint32_t kofA = ((uint32_t)(kk << 5)) | (aKh << 4);
#pragma unroll
            for (int mt = 0; mt < 4; mt++)
                ldsm4(a[mt][0], a[mt][1], a[mt][2], a[mt][3],
                      buf + aBase[mt] + (kofA ^ aSx[mt]));
            uint32_t b[4][2];
            const uint32_t kofB = ((uint32_t)(kk << 5)) | (bKh << 4);
#pragma unroll
            for (int p = 0; p < 2; p++) {
                uint32_t r0, r1, r2, r3;
                ldsm4(r0, r1, r2, r3, buf + bBase[p] + (kofB ^ bSx[p]));
                b[p * 2 + 0][0] = r0; b[p * 2 + 0][1] = r1;
                b[p * 2 + 1][0] = r2; b[p * 2 + 1][1] = r3;
            }
#pragma unroll
            for (int mt = 0; mt < 4; mt++)
#pragma unroll
                for (int nt = 0; nt < 4; nt++)
                    mma_16816(&acc[(mt * 4 + nt) * 4], a[mt], b[nt]);
        }
        if (++st >= 3) st = 0;
    }

    const int gid = lane >> 2, tig = lane & 3;
#pragma unroll
    for (int mt = 0; mt < 4; mt++) {
        int m = m0 + wm * 64 + mt * 16 + gid;
#pragma unroll
        for (int nt = 0; nt < 4; nt++) {
            int n = n0 + wn * 32 + nt * 8 + 2 * tig;
            const float* cc = &acc[(mt * 4 + nt) * 4];
            epi(m,     n, cc[0], cc[1]);
            epi(m + 8, n, cc[2], cc[3]);
        }
    }
}

// ---- fused Q/K/V projection: grid.z selects input/weight/bias/epilogue ----
__global__ void __launch_bounds__(256, 2)
hgemm_qkv(const __half* __restrict__ qkv, const __half* __restrict__ Wt,
          const float* __restrict__ bq, const float* __restrict__ bk,
          const float* __restrict__ bv,
          __half* __restrict__ Qh, __half* __restrict__ Kh,
          __half* __restrict__ Vh, __half* __restrict__ Vm)
{
    extern __shared__ char smem[];
    const uint32_t sb = smem_u32(smem);
    const int z = blockIdx.z;
    const __half* A = qkv + (size_t)z * MR * DN;
    const __half* B = Wt  + (size_t)z * DN * DN;
    const float* bias = (z == 0) ? bq : (z == 1) ? bk : bv;
    const float scale = (z == 0) ? QK_SCALE * LOG2E : 1.f;   // Q carries log2e
    __half* Ch = (z == 0) ? Qh : (z == 1) ? Kh : Vh;

    gemm_body(A, B, DN, DN, DN, sb, [&](int m, int n, float x, float y) {
        float2 bb = *(const float2*)(bias + n);
        float vx = (x + bb.x) * scale, vy = (y + bb.y) * scale;
        int bi = m >> 11, s = m & 2047;
        int h = n >> 7, dh = n & 127;
        size_t hb = (size_t)(bi * HN + h);
        __half2 hv = __floats2half2_rn(vx, vy);
        *(__half2*)(Ch + (hb * SN + s) * DHN + dh) = hv;
        if (z == 2)
            *(__half2*)(Vm + (size_t)m * DN + n) = hv;
    });
}

// ---- out = PVm @ Wo + bo - 1e9*SUF (fp32 out) ----
__global__ void __launch_bounds__(256, 2)
hgemm_out(const __half* __restrict__ A, const __half* __restrict__ Bm,
          const float* __restrict__ bias, const float* __restrict__ suf,
          float* __restrict__ C)
{
    extern __shared__ char smem[];
    const uint32_t sb = smem_u32(smem);
    gemm_body(A, Bm, DN, DN, DN, sb, [&](int m, int n, float x, float y) {
        float2 bb = *(const float2*)(bias + n);
        const float* sf = suf + (size_t)m * DN + n;
        *(float2*)(C + (size_t)m * DN + n) =
            make_float2(x + bb.x - 1e9f * sf[0], y + bb.y - 1e9f * sf[1]);
    });
}

// ========== combined launch: z=0 flash attention, z=1 U = Vm @ Wo ==========
// Both branches: 256 threads, 96KB smem, 2 CTA/SM.
// flash: grid (qt=16, bh=64). 8 warps x 16 q-rows. Bc=64 kv/iter, 32 iters.
//        smem: Q 32K, K 2x16K, V 2x16K = 96KB. exp2 domain (Q pre-scaled).
//        V stored [kv, dh] like K; PV B-fragments via ldmatrix.trans.
constexpr int FL_SMEM = 32768 + 4 * 16384;

__global__ void __launch_bounds__(256, 2)
flash_u(const __half* __restrict__ Qg, const __half* __restrict__ Kg,
        const __half* __restrict__ Vg, __half* __restrict__ PVm,
        const __half* __restrict__ Vm, const __half* __restrict__ Wto,
        float* __restrict__ U)
{
    extern __shared__ char smem[];
    const uint32_t sb = smem_u32(smem);

    if (blockIdx.z == 1) {
        gemm_body(Vm, Wto, DN, DN, DN, sb, [&](int m, int n, float x, float y) {
            *(float2*)(U + (size_t)m * DN + n) = make_float2(x, y);
        });
        return;
    }

    constexpr uint32_t QS = 0, KS = 32768, VS = 32768 + 2 * 16384;
    const int tid = threadIdx.x, wid = tid >> 5, lane = tid & 31;
    const int qt = blockIdx.x, bh = blockIdx.y;
    const int b = bh >> 4, h = bh & 15;
    const __half* Qp = Qg + (size_t)bh * SN * DHN;
    const __half* Kp = Kg + (size_t)bh * SN * DHN;
    const __half* Vp = Vg + (size_t)bh * SN * DHN;
    const int vlast = 2 * qt + 1;      // last kv tile needed for PV

    // Q tile: 128 rows x 128 dh (2 subtiles of 64 dh)
#pragma unroll
    for (int i = 0; i < 8; i++) {
        int u = tid + i * 256;
        int r = u >> 4, ku = u & 15;
        cp_async16(sb + QS + (ku >> 3) * 16384 + swz(r * 128 + (ku & 7) * 16),
                   Qp + (size_t)(qt * 128 + r) * DHN + ku * 8);
    }
    auto loadKV = [&](int kt, int stg) {
#pragma unroll
        for (int i = 0; i < 4; i++) {
            int u = tid + i * 256;
            int r = u >> 4, ku = u & 15;
            cp_async16(sb + KS + stg * 16384 + (ku >> 3) * 8192 + swz(r * 128 + (ku & 7) * 16),
                       Kp + (size_t)(kt * 64 + r) * DHN + ku * 8);
        }
        if (kt <= vlast) {
#pragma unroll
            for (int i = 0; i < 4; i++) {
                int u = tid + i * 256;
                int r = u >> 4, ku = u & 15;
                cp_async16(sb + VS + stg * 16384 + (ku >> 3) * 8192 + swz(r * 128 + (ku & 7) * 16),
                           Vp + (size_t)(kt * 64 + r) * DHN + ku * 8);
            }
        }
        cp_commit();
    };
    loadKV(0, 0);

    const int gid = lane >> 2, tig = lane & 3;
    const int am = wid * 16 + (lane & 15);
    const int aKh = (lane >> 4) & 1;
    const uint32_t aBase = am * 128, aSx = (am & 7) << 4;
    const int bKh = (lane >> 3) & 1, bN8 = (lane >> 4) & 1;
    const uint32_t laneSwz = (uint32_t)(lane & 7) << 4;
    const int kvLane = bKh * 8 + (lane & 7);

    const int q0 = qt * 128 + wid * 16 + gid;
    const int q1 = q0 + 8;
    const int qmaxw = qt * 128 + wid * 16 + 15;

    float m0r = -1e30f, m1r = -1e30f, l0 = 0.f, l1 = 0.f;
    float oacc[16][4];
#pragma unroll
    for (int i = 0; i < 16; i++)
#pragma unroll
        for (int j = 0; j < 4; j++) oacc[i][j] = 0.f;

    for (int kt = 0; kt < 32; kt++) {
        const int stg = kt & 1;
        if (kt + 1 < 32) { loadKV(kt + 1, stg ^ 1); cp_wait1(); }
        else             { cp_wait0(); }
        __syncthreads();

        // S = Q @ K^T  (16 x 64 per warp), log2-domain scores
        float sacc[8][4];
#pragma unroll
        for (int nt = 0; nt < 8; nt++)
#pragma unroll
            for (int j = 0; j < 4; j++) sacc[nt][j] = 0.f;
#pragma unroll
        for (int kk = 0; kk < 8; kk++) {
            uint32_t a[4];
            const uint32_t kofA = ((uint32_t)((kk & 3) << 5)) | (aKh << 4);
            ldsm4(a[0], a[1], a[2], a[3],
                  sb + QS + (kk >> 2) * 16384 + aBase + (kofA ^ aSx));
            const uint32_t kofB = ((uint32_t)((kk & 3) << 5)) | (bKh << 4);
            const uint32_t kb = sb + KS + stg * 16384 + (kk >> 2) * 8192;
#pragma unroll
            for (int p = 0; p < 4; p++) {
                int n = p * 16 + bN8 * 8 + (lane & 7);
                uint32_t r0, r1, r2, r3;
                ldsm4(r0, r1, r2, r3, kb + n * 128 + (kofB ^ ((n & 7) << 4)));
                uint32_t b0[2] = {r0, r1}, b1[2] = {r2, r3};
                mma_16816(sacc[p * 2 + 0], a, b0);
                mma_16816(sacc[p * 2 + 1], a, b1);
            }
        }

        // online softmax (full row, exp2 domain)
        float mx0 = -1e30f, mx1 = -1e30f;
#pragma unroll
        for (int nt = 0; nt < 8; nt++) {
            mx0 = fmaxf(mx0, fmaxf(sacc[nt][0], sacc[nt][1]));
            mx1 = fmaxf(mx1, fmaxf(sacc[nt][2], sacc[nt][3]));
        }
        mx0 = fmaxf(mx0, __shfl_xor_sync(0xffffffffu, mx0, 1));
        mx0 = fmaxf(mx0, __shfl_xor_sync(0xffffffffu, mx0, 2));
        mx1 = fmaxf(mx1, __shfl_xor_sync(0xffffffffu, mx1, 1));
        mx1 = fmaxf(mx1, __shfl_xor_sync(0xffffffffu, mx1, 2));
        float mn0 = fmaxf(m0r, mx0), mn1 = fmaxf(m1r, mx1);
        float sc0 = ex2f(m0r - mn0), sc1 = ex2f(m1r - mn1);
        m0r = mn0; m1r = mn1;
        if (__ballot_sync(0xffffffffu, (sc0 != 1.f) | (sc1 != 1.f))) {
            l0 *= sc0; l1 *= sc1;
#pragma unroll
            for (int nt = 0; nt < 16; nt++) {
                oacc[nt][0] *= sc0; oacc[nt][1] *= sc0;
                oacc[nt][2] *= sc1; oacc[nt][3] *= sc1;
            }
        }
        const int kvb = kt * 64;
        uint32_t pf[8][2];
#pragma unroll
        for (int nt = 0; nt < 8; nt++) {
            int c0 = kvb + nt * 8 + 2 * tig, c1 = c0 + 1;
            float e0 = ex2f(sacc[nt][0] - mn0), e1 = ex2f(sacc[nt][1] - mn0);
            float e2 = ex2f(sacc[nt][2] - mn1), e3 = ex2f(sacc[nt][3] - mn1);
            l0 += e0 + e1; l1 += e2 + e3;
            __half2 h01 = __floats2half2_rn(c0 <= q0 ? e0 : 0.f, c1 <= q0 ? e1 : 0.f);
            __half2 h23 = __floats2half2_rn(c0 <= q1 ? e2 : 0.f, c1 <= q1 ? e3 : 0.f);
            pf[nt][0] = *(uint32_t*)&h01;
            pf[nt][1] = *(uint32_t*)&h23;
        }

        // PV accumulate via ldmatrix.trans on [kv,dh] V tile
        if (kvb <= qmaxw) {
            const uint32_t vb = sb + VS + stg * 16384;
#pragma unroll
            for (int j = 0; j < 4; j++) {
                uint32_t a2[4] = { pf[2 * j][0], pf[2 * j][1], pf[2 * j + 1][0], pf[2 * j + 1][1] };
                const uint32_t rowoff = (uint32_t)(j * 16 + kvLane) * 128;
#pragma unroll
                for (int p = 0; p < 8; p++) {
                    int dhseg = p * 16 + bN8 * 8;
                    uint32_t addr = vb + ((dhseg >> 6) * 8192) + rowoff
                                    + (((uint32_t)(dhseg & 63) * 2) ^ laneSwz);
                    uint32_t r0, r1, r2, r3;
                    ldsm4t(r0, r1, r2, r3, addr);
                    uint32_t b0[2] = {r0, r1}, b1[2] = {r2, r3};
                    mma_16816(oacc[p * 2 + 0], a2, b0);
                    mma_16816(oacc[p * 2 + 1], a2, b1);
                }
            }
        }
        __syncthreads();   // protect the buffer loaded next iter
    }

    // finalize
    l0 += __shfl_xor_sync(0xffffffffu, l0, 1);
    l0 += __shfl_xor_sync(0xffffffffu, l0, 2);
    l1 += __shfl_xor_sync(0xffffffffu, l1, 1);
    l1 += __shfl_xor_sync(0xffffffffu, l1, 2);
    const float i0 = 1.f / l0, i1 = 1.f / l1;
#pragma unroll
    for (int nt = 0; nt < 16; nt++) {
        int dh = nt * 8 + 2 * tig;
        __half2 ha = __floats2half2_rn(oacc[nt][0] * i0, oacc[nt][1] * i0);
        __half2 hb = __floats2half2_rn(oacc[nt][2] * i1, oacc[nt][3] * i1);
        *(__half2*)(PVm + ((size_t)(b * SN) + q0) * DN + h * 128 + dh) = ha;
        *(__half2*)(PVm + ((size_t)(b * SN) + q1) * DN + h * 128 + dh) = hb;
    }
}

// ---------------- fused prepass: fp32->fp16 converts + weight transposes ----------------
// grid (16384, 4): y<3 = convert q/k/v slice y; y=3 = transpose tile of one weight.
__global__ void __launch_bounds__(256)
prepass(const float* __restrict__ q, const float* __restrict__ k,
        const float* __restrict__ v,
        const float* __restrict__ W0, const float* __restrict__ W1,
        const float* __restrict__ W2, const float* __restrict__ W3,
        __half* __restrict__ qkvh, __half* __restrict__ Wt)
{
    __shared__ float t[32][33];
    if (blockIdx.y < 3) {
        const float* x = (blockIdx.y == 0) ? q : (blockIdx.y == 1) ? k : v;
        size_t i = (size_t)blockIdx.x * 256 + threadIdx.x;
        float4 vv = ((const float4*)x)[i];
        __half2 h0 = __floats2half2_rn(vv.x, vv.y);
        __half2 h1 = __floats2half2_rn(vv.z, vv.w);
        ((uint2*)(qkvh + (size_t)blockIdx.y * MR * DN))[i] =
            make_uint2(*(uint32_t*)&h0, *(uint32_t*)&h1);
        return;
    }
    int u = blockIdx.x;              // 0..16383 = 4 weights x 64 x 64 tiles
    int w = u >> 12, rem = u & 4095;
    int k0 = (rem >> 6) * 32, n0 = (rem & 63) * 32;
    const float* W = (w == 0) ? W0 : (w == 1) ? W1 : (w == 2) ? W2 : W3;
    __half* Wo = Wt + (size_t)w * DN * DN;
    int tx = threadIdx.x & 31, ty = threadIdx.x >> 5;
#pragma unroll
    for (int j = ty; j < 32; j += 8)
        t[j][tx] = W[(size_t)(k0 + j) * DN + n0 + tx];
    __syncthreads();
#pragma unroll
    for (int j = ty; j < 32; j += 8)
        Wo[(size_t)(n0 + j) * DN + k0 + tx] = __float2half_rn(t[tx][j]);
}

// ---------------- suffix sums of U over s ----------------
__global__ void __launch_bounds__(256)
suf_pass1(const float* __restrict__ U, float* __restrict__ seg)
{
    int b = blockIdx.x, sg = blockIdx.y;
    int d = blockIdx.z * 256 + threadIdx.x;
    const float* u = U + ((size_t)b * SN + sg * 128) * DN + d;
    float a = 0.f;
#pragma unroll 8
    for (int i = 0; i < 128; i++) a += u[(size_t)i * DN];
    seg[((size_t)b * 16 + sg) * DN + d] = a;
}

__global__ void __launch_bounds__(256)
suf_pass2(const float* __restrict__ U, const float* __restrict__ seg,
          float* __restrict__ SUF)
{
    int b = blockIdx.x, sg = blockIdx.y;
    int d = blockIdx.z * 256 + threadIdx.x;
    float off = 0.f;
    for (int j = sg + 1; j < 16; j++) off += seg[((size_t)b * 16 + j) * DN + d];
    const float* u = U + ((size_t)b * SN + sg * 128) * DN + d;
    float* o = SUF + ((size_t)b * SN + sg * 128) * DN + d;
    float a = off;
    for (int i = 127; i >= 0; i--) {
        o[(size_t)i * DN] = a;
        a += u[(size_t)i * DN];
    }
}

// ---------------- launch ----------------
extern "C" void kernel_launch(void* const* d_in, const int* in_sizes, int n_in,
                              void* d_out, int out_size)
{
    const float* q  = (const float*)d_in[0];
    const float* k  = (const float*)d_in[1];
    const float* v  = (const float*)d_in[2];
    const float* Wq = (const float*)d_in[3];
    const float* bq = (const float*)d_in[4];
    const float* Wk = (const float*)d_in[5];
    const float* bk = (const float*)d_in[6];
    const float* Wv = (const float*)d_in[7];
    const float* bv = (const float*)d_in[8];
    const float* Wo = (const float*)d_in[9];
    const float* bo = (const float*)d_in[10];
    float* out = (float*)d_out;

    void *p;
    __half *qkvh, *Wt, *Qh, *Kh, *Vh, *Vm, *PVm;
    float *U, *SUF, *SEG;
    cudaGetSymbolAddress(&p, g_qkvh); qkvh = (__half*)p;
    cudaGetSymbolAddress(&p, g_Wt);   Wt   = (__half*)p;
    cudaGetSymbolAddress(&p, g_Q);    Qh   = (__half*)p;
    cudaGetSymbolAddress(&p, g_K);    Kh   = (__half*)p;
    cudaGetSymbolAddress(&p, g_Vh);   Vh   = (__half*)p;
    cudaGetSymbolAddress(&p, g_Vm);   Vm   = (__half*)p;
    cudaGetSymbolAddress(&p, g_PVm);  PVm  = (__half*)p;
    cudaGetSymbolAddress(&p, g_U);    U    = (float*)p;
    cudaGetSymbolAddress(&p, g_SUF);  SUF  = (float*)p;
    cudaGetSymbolAddress(&p, g_SEG);  SEG  = (float*)p;
    __half* Wto = Wt + 3 * (size_t)DN * DN;

    cudaFuncSetAttribute(hgemm_qkv, cudaFuncAttributeMaxDynamicSharedMemorySize, GM_SMEM);
    cudaFuncSetAttribute(hgemm_out, cudaFuncAttributeMaxDynamicSharedMemorySize, GM_SMEM);
    cudaFuncSetAttribute(flash_u,   cudaFuncAttributeMaxDynamicSharedMemorySize, FL_SMEM);

    // 0) fused prepass: convert q/k/v to fp16 + transpose/convert weights
    dim3 gP(16384, 4);
    prepass<<<gP, 256>>>(q, k, v, Wq, Wk, Wv, Wo, qkvh, Wt);

    // 1) fused Q/K/V projections (Q pre-scaled by log2e/sqrt(DH))
    dim3 gProj(DN / 128, MR / 128, 3);   // (16, 64, 3)
    hgemm_qkv<<<gProj, 256, GM_SMEM>>>(qkvh, Wt, bq, bk, bv, Qh, Kh, Vh, Vm);

    // 2) combined: flash attention (z=0) + U = Vm @ Wo (z=1)
    dim3 gFU(16, 64, 2);
    flash_u<<<gFU, 256, FL_SMEM>>>(Qh, Kh, Vh, PVm, Vm, Wto, U);

    // 3) suffix sums of U (post-softmax mask correction)
    dim3 gSuf(BN, 16, DN / 256);
    suf_pass1<<<gSuf, 256>>>(U, SEG);
    suf_pass2<<<gSuf, 256>>>(U, SEG, SUF);

    // 4) out = PVm @ Wo + bo - 1e9 * SUF
    dim3 gU(DN / 128, MR / 128);
    hgemm_out<<<gU, 256, GM_SMEM>>>(PVm, Wto, bo, SUF, out);
}

// round 14
// speedup vs baseline: 1.0075x; 1.0075x over previous
#include <cuda_runtime.h>
#include <cuda_fp16.h>
#include <cstdint>
#include <math.h>

// ---------------- problem constants ----------------
constexpr int BN  = 4;
constexpr int SN  = 2048;
constexpr int DN  = 2048;
constexpr int HN  = 16;
constexpr int DHN = 128;
constexpr int BH  = BN * HN;      // 64
constexpr int MR  = BN * SN;      // 8192
constexpr float QK_SCALE = 0.08838834764831845f;
constexpr float LOG2E    = 1.4426950408889634f;

// ---------------- static device scratch ----------------
__device__ __half g_qkvh[3][(size_t)MR * DN];     // fp16 q,k,v
__device__ __half g_Wt  [4][(size_t)DN * DN];     // transposed fp16 Wq,Wk,Wv,Wo
__device__ __half g_Q  [(size_t)BH * SN * DHN];   // [bh,s,dh] fp16 (pre-scaled, log2 domain)
__device__ __half g_K  [(size_t)BH * SN * DHN];   // [bh,s,dh]
__device__ __half g_Vh [(size_t)BH * SN * DHN];   // [bh,s,dh] (flash uses ldmatrix.trans)
__device__ __half g_Vm [(size_t)MR * DN];         // merged V proj [B,S,D]
__device__ __half g_SVh[(size_t)MR * DN];         // suffix sums of Vm, fp16
__device__ __half g_PVm[(size_t)MR * DN];         // merged PV [B,S,D]
__device__ float  g_SUF[(size_t)MR * DN];         // SVh @ Wo  (= suffix of Vm@Wo)
__device__ float  g_SEG[(size_t)BN * 16 * DN];

// ---------------- helpers ----------------
__device__ __forceinline__ uint32_t smem_u32(const void* p) {
    uint32_t a;
    asm("{ .reg .u64 t; cvta.to.shared.u64 t, %1; cvt.u32.u64 %0, t; }" : "=r"(a) : "l"(p));
    return a;
}
__device__ __forceinline__ float ex2f(float x) {
    float y;
    asm("ex2.approx.ftz.f32 %0, %1;" : "=f"(y) : "f"(x));
    return y;
}
__device__ __forceinline__ void cp_async16(uint32_t dst, const void* src) {
    asm volatile("cp.async.cg.shared.global [%0], [%1], 16;" :: "r"(dst), "l"(src));
}
__device__ __forceinline__ void cp_commit() { asm volatile("cp.async.commit_group;"); }
__device__ __forceinline__ void cp_wait0()  { asm volatile("cp.async.wait_group 0;"); }
__device__ __forceinline__ void cp_wait1()  { asm volatile("cp.async.wait_group 1;"); }
__device__ __forceinline__ uint32_t swz(uint32_t off) {
    return off ^ ((off >> 3) & 0x70);
}
__device__ __forceinline__ void ldsm4(uint32_t& r0, uint32_t& r1, uint32_t& r2, uint32_t& r3,
                                      uint32_t addr) {
    asm volatile("ldmatrix.sync.aligned.m8n8.x4.shared.b16 {%0,%1,%2,%3}, [%4];"
        : "=r"(r0), "=r"(r1), "=r"(r2), "=r"(r3) : "r"(addr));
}
__device__ __forceinline__ void ldsm4t(uint32_t& r0, uint32_t& r1, uint32_t& r2, uint32_t& r3,
                                       uint32_t addr) {
    asm volatile("ldmatrix.sync.aligned.m8n8.x4.trans.shared.b16 {%0,%1,%2,%3}, [%4];"
        : "=r"(r0), "=r"(r1), "=r"(r2), "=r"(r3) : "r"(addr));
}
__device__ __forceinline__ void mma_16816(float* c, const uint32_t* a, const uint32_t* b) {
    asm volatile("mma.sync.aligned.m16n8k16.row.col.f32.f16.f16.f32 "
        "{%0,%1,%2,%3},{%4,%5,%6,%7},{%8,%9},{%0,%1,%2,%3};"
        : "+f"(c[0]), "+f"(c[1]), "+f"(c[2]), "+f"(c[3])
        : "r"(a[0]), "r"(a[1]), "r"(a[2]), "r"(a[3]), "r"(b[0]), "r"(b[1]));
}

// ================= GEMM core (128x128 CTA tile, 3-stage, 2 CTA/SM) =================
constexpr int GM_STAGE = 32768;            // A 16KB + B 16KB
constexpr int GM_SMEM  = 3 * GM_STAGE;     // 96KB

template<typename EpiFn>
__device__ __forceinline__ void gemm_body(
    const __half* __restrict__ A, const __half* __restrict__ Bm,
    int K, int lda, int ldb, uint32_t sb, EpiFn epi)
{
    const int tid = threadIdx.x, wid = tid >> 5, lane = tid & 31;
    const int wm = wid >> 2, wn = wid & 3;           // 2x4 warp grid
    const int m0 = blockIdx.y * 128, n0 = blockIdx.x * 128;

    float acc[64];
#pragma unroll
    for (int i = 0; i < 64; i++) acc[i] = 0.f;

    const int CC = K >> 6;   // 64-half chunks

    auto load_chunk = [&](int st, int c) {
        int k0 = c << 6;
        const uint32_t sa = sb + st * GM_STAGE;
#pragma unroll
        for (int i = 0; i < 4; i++) {
            int u = tid + i * 256;
            int r = u >> 3, ku = u & 7;
            cp_async16(sa + swz(r * 128 + ku * 16),
                       A + (size_t)(m0 + r) * lda + k0 + ku * 8);
        }
#pragma unroll
        for (int i = 0; i < 4; i++) {
            int u = tid + i * 256;
            int r = u >> 3, ku = u & 7;
            cp_async16(sa + 16384 + swz(r * 128 + ku * 16),
                       Bm + (size_t)(n0 + r) * ldb + k0 + ku * 8);
        }
        cp_commit();
    };

    const int row16 = lane & 15;
    const int aKh   = (lane >> 4) & 1;
    uint32_t aBase[4], aSx[4];
#pragma unroll
    for (int mt = 0; mt < 4; mt++) {
        int m = wm * 64 + mt * 16 + row16;
        aBase[mt] = m * 128;
        aSx[mt] = (m & 7) << 4;
    }
    const int bKh   = (lane >> 3) & 1;
    const int bN8   = (lane >> 4) & 1;
    uint32_t bBase[2], bSx[2];
#pragma unroll
    for (int p = 0; p < 2; p++) {
        int n = wn * 32 + p * 16 + bN8 * 8 + (lane & 7);
        bBase[p] = 16384 + n * 128;
        bSx[p] = (n & 7) << 4;
    }

    load_chunk(0, 0);
    load_chunk(1, 1);
    int st = 0;
    for (int c = 0; c < CC; c++) {
        if (c < CC - 1) cp_wait1(); else cp_wait0();
        __syncthreads();
        if (c + 2 < CC) {
            int st2 = st + 2; if (st2 >= 3) st2 -= 3;
            load_chunk(st2, c + 2);
        }
        const uint32_t buf = sb + st * GM_STAGE;
#pragma unroll
        for (int kk = 0; kk < 4; kk++) {
            uint32_t a[4][4];
            const uint32_t kofA = ((uint32_t)(kk << 5)) | (aKh << 4);
#pragma unroll
            for (int mt = 0; mt < 4; mt++)
                ldsm4(a[mt][0], a[mt][1], a[mt][2], a[mt][3],
                      buf + aBase[mt] + (kofA ^ aSx[mt]));
            uint32_t b[4][2];
            const uint32_t kofB = ((uint32_t)(kk << 5)) | (bKh << 4);
#pragma unroll
            for (int p = 0; p < 2; p++) {
                uint32_t r0, r1, r2, r3;
                ldsm4(r0, r1, r2, r3, buf + bBase[p] + (kofB ^ bSx[p]));
                b[p * 2 + 0][0] = r0; b[p * 2 + 0][1] = r1;
                b[p * 2 + 1][0] = r2; b[p * 2 + 1][1] = r3;
            }
#pragma unroll
            for (int mt = 0; mt < 4; mt++)
#pragma unroll
                for (int nt = 0; nt < 4; nt++)
                    mma_16816(&acc[(mt * 4 + nt) * 4], a[mt], b[nt]);
        }
        if (++st >= 3) st = 0;
    }

    const int gid = lane >> 2, tig = lane & 3;
#pragma unroll
    for (int mt = 0; mt < 4; mt++) {
        int m = m0 + wm * 64 + mt * 16 + gid;
#pragma unroll
        for (int nt = 0; nt < 4; nt++) {
            int n = n0 + wn * 32 + nt * 8 + 2 * tig;
            const float* cc = &acc[(mt * 4 + nt) * 4];
            epi(m,     n, cc[0], cc[1]);
            epi(m + 8, n, cc[2], cc[3]);
        }
    }
}

// ---- fused Q/K/V projection: grid.z selects input/weight/bias/epilogue ----
__global__ void __launch_bounds__(256, 2)
hgemm_qkv(const __half* __restrict__ qkv, const __half* __restrict__ Wt,
          const float* __restrict__ bq, const float* __restrict__ bk,
          const float* __restrict__ bv,
          __half* __restrict__ Qh, __half* __restrict__ Kh,
          __half* __restrict__ Vh, __half* __restrict__ Vm)
{
    extern __shared__ char smem[];
    const uint32_t sb = smem_u32(smem);
    const int z = blockIdx.z;
    const __half* A = qkv + (size_t)z * MR * DN;
    const __half* B = Wt  + (size_t)z * DN * DN;
    const float* bias = (z == 0) ? bq : (z == 1) ? bk : bv;
    const float scale = (z == 0) ? QK_SCALE * LOG2E : 1.f;   // Q carries log2e
    __half* Ch = (z == 0) ? Qh : (z == 1) ? Kh : Vh;

    gemm_body(A, B, DN, DN, DN, sb, [&](int m, int n, float x, float y) {
        float2 bb = *(const float2*)(bias + n);
        float vx = (x + bb.x) * scale, vy = (y + bb.y) * scale;
        int bi = m >> 11, s = m & 2047;
        int h = n >> 7, dh = n & 127;
        size_t hb = (size_t)(bi * HN + h);
        __half2 hv = __floats2half2_rn(vx, vy);
        *(__half2*)(Ch + (hb * SN + s) * DHN + dh) = hv;
        if (z == 2)
            *(__half2*)(Vm + (size_t)m * DN + n) = hv;
    });
}

// ---- out = PVm @ Wo + bo - 1e9*SUF (fp32 out) ----
__global__ void __launch_bounds__(256, 2)
hgemm_out(const __half* __restrict__ A, const __half* __restrict__ Bm,
          const float* __restrict__ bias, const float* __restrict__ suf,
          float* __restrict__ C)
{
    extern __shared__ char smem[];
    const uint32_t sb = smem_u32(smem);
    gemm_body(A, Bm, DN, DN, DN, sb, [&](int m, int n, float x, float y) {
        float2 bb = *(const float2*)(bias + n);
        const float* sf = suf + (size_t)m * DN + n;
        *(float2*)(C + (size_t)m * DN + n) =
            make_float2(x + bb.x - 1e9f * sf[0], y + bb.y - 1e9f * sf[1]);
    });
}

// ========== combined launch: z=0 flash attention, z=1 SUF = SVh @ Wo ==========
// Both branches: 256 threads, 96KB smem, 2 CTA/SM.
// flash: grid (qt=16, bh=64). 8 warps x 16 q-rows. Bc=64 kv/iter, 32 iters.
//        smem: Q 32K, K 2x16K, V 2x16K = 96KB. exp2 domain (Q pre-scaled).
//        V stored [kv, dh] like K; PV B-fragments via ldmatrix.trans.
constexpr int FL_SMEM = 32768 + 4 * 16384;

__global__ void __launch_bounds__(256, 2)
flash_u(const __half* __restrict__ Qg, const __half* __restrict__ Kg,
        const __half* __restrict__ Vg, __half* __restrict__ PVm,
        const __half* __restrict__ SVh, const __half* __restrict__ Wto,
        float* __restrict__ SUF)
{
    extern __shared__ char smem[];
    const uint32_t sb = smem_u32(smem);

    if (blockIdx.z == 1) {
        gemm_body(SVh, Wto, DN, DN, DN, sb, [&](int m, int n, float x, float y) {
            *(float2*)(SUF + (size_t)m * DN + n) = make_float2(x, y);
        });
        return;
    }

    constexpr uint32_t QS = 0, KS = 32768, VS = 32768 + 2 * 16384;
    const int tid = threadIdx.x, wid = tid >> 5, lane = tid & 31;
    const int qt = blockIdx.x, bh = blockIdx.y;
    const int b = bh >> 4, h = bh & 15;
    const __half* Qp = Qg + (size_t)bh * SN * DHN;
    const __half* Kp = Kg + (size_t)bh * SN * DHN;
    const __half* Vp = Vg + (size_t)bh * SN * DHN;
    const int vlast = 2 * qt + 1;      // last kv tile needed for PV

    // Q tile: 128 rows x 128 dh (2 subtiles of 64 dh)
#pragma unroll
    for (int i = 0; i < 8; i++) {
        int u = tid + i * 256;
        int r = u >> 4, ku = u & 15;
        cp_async16(sb + QS + (ku >> 3) * 16384 + swz(r * 128 + (ku & 7) * 16),
                   Qp + (size_t)(qt * 128 + r) * DHN + ku * 8);
    }
    auto loadKV = [&](int kt, int stg) {
#pragma unroll
        for (int i = 0; i < 4; i++) {
            int u = tid + i * 256;
            int r = u >> 4, ku = u & 15;
            cp_async16(sb + KS + stg * 16384 + (ku >> 3) * 8192 + swz(r * 128 + (ku & 7) * 16),
                       Kp + (size_t)(kt * 64 + r) * DHN + ku * 8);
        }
        if (kt <= vlast) {
#pragma unroll
            for (int i = 0; i < 4; i++) {
                int u = tid + i * 256;
                int r = u >> 4, ku = u & 15;
                cp_async16(sb + VS + stg * 16384 + (ku >> 3) * 8192 + swz(r * 128 + (ku & 7) * 16),
                           Vp + (size_t)(kt * 64 + r) * DHN + ku * 8);
            }
        }
        cp_commit();
    };
    loadKV(0, 0);

    const int gid = lane >> 2, tig = lane & 3;
    const int am = wid * 16 + (lane & 15);
    const int aKh = (lane >> 4) & 1;
    const uint32_t aBase = am * 128, aSx = (am & 7) << 4;
    const int bKh = (lane >> 3) & 1, bN8 = (lane >> 4) & 1;
    const uint32_t laneSwz = (uint32_t)(lane & 7) << 4;
    const int kvLane = bKh * 8 + (lane & 7);

    const int q0 = qt * 128 + wid * 16 + gid;
    const int q1 = q0 + 8;
    const int qmaxw = qt * 128 + wid * 16 + 15;

    float m0r = -1e30f, m1r = -1e30f, l0 = 0.f, l1 = 0.f;
    float oacc[16][4];
#pragma unroll
    for (int i = 0; i < 16; i++)
#pragma unroll
        for (int j = 0; j < 4; j++) oacc[i][j] = 0.f;

    for (int kt = 0; kt < 32; kt++) {
        const int stg = kt & 1;
        if (kt + 1 < 32) { loadKV(kt + 1, stg ^ 1); cp_wait1(); }
        else             { cp_wait0(); }
        __syncthreads();

        // S = Q @ K^T  (16 x 64 per warp), log2-domain scores
        float sacc[8][4];
#pragma unroll
        for (int nt = 0; nt < 8; nt++)
#pragma unroll
            for (int j = 0; j < 4; j++) sacc[nt][j] = 0.f;
#pragma unroll
        for (int kk = 0; kk < 8; kk++) {
            uint32_t a[4];
            const uint32_t kofA = ((uint32_t)((kk & 3) << 5)) | (aKh << 4);
            ldsm4(a[0], a[1], a[2], a[3],
                  sb + QS + (kk >> 2) * 16384 + aBase + (kofA ^ aSx));
            const uint32_t kofB = ((uint32_t)((kk & 3) << 5)) | (bKh << 4);
            const uint32_t kb = sb + KS + stg * 16384 + (kk >> 2) * 8192;
#pragma unroll
            for (int p = 0; p < 4; p++) {
                int n = p * 16 + bN8 * 8 + (lane & 7);
                uint32_t r0, r1, r2, r3;
                ldsm4(r0, r1, r2, r3, kb + n * 128 + (kofB ^ ((n & 7) << 4)));
                uint32_t b0[2] = {r0, r1}, b1[2] = {r2, r3};
                mma_16816(sacc[p * 2 + 0], a, b0);
                mma_16816(sacc[p * 2 + 1], a, b1);
            }
        }

        // online softmax (full row, exp2 domain)
        float mx0 = -1e30f, mx1 = -1e30f;
#pragma unroll
        for (int nt = 0; nt < 8; nt++) {
            mx0 = fmaxf(mx0, fmaxf(sacc[nt][0], sacc[nt][1]));
            mx1 = fmaxf(mx1, fmaxf(sacc[nt][2], sacc[nt][3]));
        }
        mx0 = fmaxf(mx0, __shfl_xor_sync(0xffffffffu, mx0, 1));
        mx0 = fmaxf(mx0, __shfl_xor_sync(0xffffffffu, mx0, 2));
        mx1 = fmaxf(mx1, __shfl_xor_sync(0xffffffffu, mx1, 1));
        mx1 = fmaxf(mx1, __shfl_xor_sync(0xffffffffu, mx1, 2));
        float mn0 = fmaxf(m0r, mx0), mn1 = fmaxf(m1r, mx1);
        float sc0 = ex2f(m0r - mn0), sc1 = ex2f(m1r - mn1);
        m0r = mn0; m1r = mn1;
        if (__ballot_sync(0xffffffffu, (sc0 != 1.f) | (sc1 != 1.f))) {
            l0 *= sc0; l1 *= sc1;
#pragma unroll
            for (int nt = 0; nt < 16; nt++) {
                oacc[nt][0] *= sc0; oacc[nt][1] *= sc0;
                oacc[nt][2] *= sc1; oacc[nt][3] *= sc1;
            }
        }
        const int kvb = kt * 64;
        uint32_t pf[8][2];
#pragma unroll
        for (int nt = 0; nt < 8; nt++) {
            int c0 = kvb + nt * 8 + 2 * tig, c1 = c0 + 1;
            float e0 = ex2f(sacc[nt][0] - mn0), e1 = ex2f(sacc[nt][1] - mn0);
            float e2 = ex2f(sacc[nt][2] - mn1), e3 = ex2f(sacc[nt][3] - mn1);
            l0 += e0 + e1; l1 += e2 + e3;
            __half2 h01 = __floats2half2_rn(c0 <= q0 ? e0 : 0.f, c1 <= q0 ? e1 : 0.f);
            __half2 h23 = __floats2half2_rn(c0 <= q1 ? e2 : 0.f, c1 <= q1 ? e3 : 0.f);
            pf[nt][0] = *(uint32_t*)&h01;
            pf[nt][1] = *(uint32_t*)&h23;
        }

        // PV accumulate via ldmatrix.trans on [kv,dh] V tile
        if (kvb <= qmaxw) {
            const uint32_t vb = sb + VS + stg * 16384;
#pragma unroll
            for (int j = 0; j < 4; j++) {
                uint32_t a2[4] = { pf[2 * j][0], pf[2 * j][1], pf[2 * j + 1][0], pf[2 * j + 1][1] };
                const uint32_t rowoff = (uint32_t)(j * 16 + kvLane) * 128;
#pragma unroll
                for (int p = 0; p < 8; p++) {
                    int dhseg = p * 16 + bN8 * 8;
                    uint32_t addr = vb + ((dhseg >> 6) * 8192) + rowoff
                                    + (((uint32_t)(dhseg & 63) * 2) ^ laneSwz);
                    uint32_t r0, r1, r2, r3;
                    ldsm4t(r0, r1, r2, r3, addr);
                    uint32_t b0[2] = {r0, r1}, b1[2] = {r2, r3};
                    mma_16816(oacc[p * 2 + 0], a2, b0);
                    mma_16816(oacc[p * 2 + 1], a2, b1);
                }
            }
        }
        __syncthreads();   // protect the buffer loaded next iter
    }

    // finalize
    l0 += __shfl_xor_sync(0xffffffffu, l0, 1);
    l0 += __shfl_xor_sync(0xffffffffu, l0, 2);
    l1 += __shfl_xor_sync(0xffffffffu, l1, 1);
    l1 += __shfl_xor_sync(0xffffffffu, l1, 2);
    const float i0 = 1.f / l0, i1 = 1.f / l1;
#pragma unroll
    for (int nt = 0; nt < 16; nt++) {
        int dh = nt * 8 + 2 * tig;
        __half2 ha = __floats2half2_rn(oacc[nt][0] * i0, oacc[nt][1] * i0);
        __half2 hb = __floats2half2_rn(oacc[nt][2] * i1, oacc[nt][3] * i1);
        *(__half2*)(PVm + ((size_t)(b * SN) + q0) * DN + h * 128 + dh) = ha;
        *(__half2*)(PVm + ((size_t)(b * SN) + q1) * DN + h * 128 + dh) = hb;
    }
}

// ---------------- fused prepass: fp32->fp16 converts + weight transposes ----------------
// grid (16384, 4): y<3 = convert q/k/v slice y; y=3 = transpose tile of one weight.
__global__ void __launch_bounds__(256)
prepass(const float* __restrict__ q, const float* __restrict__ k,
        const float* __restrict__ v,
        const float* __restrict__ W0, const float* __restrict__ W1,
        const float* __restrict__ W2, const float* __restrict__ W3,
        __half* __restrict__ qkvh, __half* __restrict__ Wt)
{
    __shared__ float t[32][33];
    if (blockIdx.y < 3) {
        const float* x = (blockIdx.y == 0) ? q : (blockIdx.y == 1) ? k : v;
        size_t i = (size_t)blockIdx.x * 256 + threadIdx.x;
        float4 vv = ((const float4*)x)[i];
        __half2 h0 = __floats2half2_rn(vv.x, vv.y);
        __half2 h1 = __floats2half2_rn(vv.z, vv.w);
        ((uint2*)(qkvh + (size_t)blockIdx.y * MR * DN))[i] =
            make_uint2(*(uint32_t*)&h0, *(uint32_t*)&h1);
        return;
    }
    int u = blockIdx.x;              // 0..16383 = 4 weights x 64 x 64 tiles
    int w = u >> 12, rem = u & 4095;
    int k0 = (rem >> 6) * 32, n0 = (rem & 63) * 32;
    const float* W = (w == 0) ? W0 : (w == 1) ? W1 : (w == 2) ? W2 : W3;
    __half* Wo = Wt + (size_t)w * DN * DN;
    int tx = threadIdx.x & 31, ty = threadIdx.x >> 5;
#pragma unroll
    for (int j = ty; j < 32; j += 8)
        t[j][tx] = W[(size_t)(k0 + j) * DN + n0 + tx];
    __syncthreads();
#pragma unroll
    for (int j = ty; j < 32; j += 8)
        Wo[(size_t)(n0 + j) * DN + k0 + tx] = __float2half_rn(t[tx][j]);
}

// ---------------- suffix sums of Vm (fp16) over s -> SVh (fp16) ----------------
__global__ void __launch_bounds__(256)
suf_pass1(const __half* __restrict__ Vm, float* __restrict__ seg)
{
    int b = blockIdx.x, sg = blockIdx.y;
    int d = blockIdx.z * 256 + threadIdx.x;
    const __half* u = Vm + ((size_t)b * SN + sg * 128) * DN + d;
    float a = 0.f;
#pragma unroll 8
    for (int i = 0; i < 128; i++) a += __half2float(u[(size_t)i * DN]);
    seg[((size_t)b * 16 + sg) * DN + d] = a;
}

__global__ void __launch_bounds__(256)
suf_pass2(const __half* __restrict__ Vm, const float* __restrict__ seg,
          __half* __restrict__ SVh)
{
    int b = blockIdx.x, sg = blockIdx.y;
    int d = blockIdx.z * 256 + threadIdx.x;
    float off = 0.f;
    for (int j = sg + 1; j < 16; j++) off += seg[((size_t)b * 16 + j) * DN + d];
    const __half* u = Vm + ((size_t)b * SN + sg * 128) * DN + d;
    __half* o = SVh + ((size_t)b * SN + sg * 128) * DN + d;
    float a = off;
    for (int i = 127; i >= 0; i--) {
        o[(size_t)i * DN] = __float2half_rn(a);
        a += __half2float(u[(size_t)i * DN]);
    }
}

// ---------------- launch ----------------
extern "C" void kernel_launch(void* const* d_in, const int* in_sizes, int n_in,
                              void* d_out, int out_size)
{
    const float* q  = (const float*)d_in[0];
    const float* k  = (const float*)d_in[1];
    const float* v  = (const float*)d_in[2];
    const float* Wq = (const float*)d_in[3];
    const float* bq = (const float*)d_in[4];
    const float* Wk = (const float*)d_in[5];
    const float* bk = (const float*)d_in[6];
    const float* Wv = (const float*)d_in[7];
    const float* bv = (const float*)d_in[8];
    const float* Wo = (const float*)d_in[9];
    const float* bo = (const float*)d_in[10];
    float* out = (float*)d_out;

    void *p;
    __half *qkvh, *Wt, *Qh, *Kh, *Vh, *Vm, *SVh, *PVm;
    float *SUF, *SEG;
    cudaGetSymbolAddress(&p, g_qkvh); qkvh = (__half*)p;
    cudaGetSymbolAddress(&p, g_Wt);   Wt   = (__half*)p;
    cudaGetSymbolAddress(&p, g_Q);    Qh   = (__half*)p;
    cudaGetSymbolAddress(&p, g_K);    Kh   = (__half*)p;
    cudaGetSymbolAddress(&p, g_Vh);   Vh   = (__half*)p;
    cudaGetSymbolAddress(&p, g_Vm);   Vm   = (__half*)p;
    cudaGetSymbolAddress(&p, g_SVh);  SVh  = (__half*)p;
    cudaGetSymbolAddress(&p, g_PVm);  PVm  = (__half*)p;
    cudaGetSymbolAddress(&p, g_SUF);  SUF  = (float*)p;
    cudaGetSymbolAddress(&p, g_SEG);  SEG  = (float*)p;
    __half* Wto = Wt + 3 * (size_t)DN * DN;

    cudaFuncSetAttribute(hgemm_qkv, cudaFuncAttributeMaxDynamicSharedMemorySize, GM_SMEM);
    cudaFuncSetAttribute(hgemm_out, cudaFuncAttributeMaxDynamicSharedMemorySize, GM_SMEM);
    cudaFuncSetAttribute(flash_u,   cudaFuncAttributeMaxDynamicSharedMemorySize, FL_SMEM);

    // 0) fused prepass: convert q/k/v to fp16 + transpose/convert weights
    dim3 gP(16384, 4);
    prepass<<<gP, 256>>>(q, k, v, Wq, Wk, Wv, Wo, qkvh, Wt);

    // 1) fused Q/K/V projections (Q pre-scaled by log2e/sqrt(DH))
    dim3 gProj(DN / 128, MR / 128, 3);   // (16, 64, 3)
    hgemm_qkv<<<gProj, 256, GM_SMEM>>>(qkvh, Wt, bq, bk, bv, Qh, Kh, Vh, Vm);

    // 2) suffix sums of Vm -> SVh (fp16; exploits suffix(Vm)@Wo == suffix(Vm@Wo))
    dim3 gSuf(BN, 16, DN / 256);
    suf_pass1<<<gSuf, 256>>>(Vm, SEG);
    suf_pass2<<<gSuf, 256>>>(Vm, SEG, SVh);

    // 3) combined: flash attention (z=0) + SUF = SVh @ Wo (z=1)
    dim3 gFU(16, 64, 2);
    flash_u<<<gFU, 256, FL_SMEM>>>(Qh, Kh, Vh, PVm, SVh, Wto, SUF);

    // 4) out = PVm @ Wo + bo - 1e9 * SUF
    dim3 gU(DN / 128, MR / 128);
    hgemm_out<<<gU, 256, GM_SMEM>>>(PVm, Wto, bo, SUF, out);
}

// round 15
// speedup vs baseline: 1.0360x; 1.0283x over previous
#include <cuda_runtime.h>
#include <cuda_fp16.h>
#include <cstdint>
#include <math.h>

// ---------------- problem constants ----------------
constexpr int BN  = 4;
constexpr int SN  = 2048;
constexpr int DN  = 2048;
constexpr int HN  = 16;
constexpr int DHN = 128;
constexpr int BH  = BN * HN;      // 64
constexpr int MR  = BN * SN;      // 8192
constexpr float QK_SCALE = 0.08838834764831845f;
constexpr float LOG2E    = 1.4426950408889634f;

// ---------------- static device scratch ----------------
__device__ __half g_qkvh[3][(size_t)MR * DN];     // fp16 q,k,v
__device__ __half g_Wt  [4][(size_t)DN * DN];     // transposed fp16 Wq,Wk,Wv,Wo
__device__ __half g_Q  [(size_t)BH * SN * DHN];   // [bh,s,dh] fp16 (pre-scaled, log2 domain)
__device__ __half g_K  [(size_t)BH * SN * DHN];   // [bh,s,dh]
__device__ __half g_Vh [(size_t)BH * SN * DHN];   // [bh,s,dh]
__device__ __half g_SVh[(size_t)MR * DN];         // suffix sums of V-proj, merged [B,S,D] fp16
__device__ __half g_PVm[(size_t)MR * DN];         // merged PV [B,S,D]
__device__ float  g_SUF[(size_t)MR * DN];         // SVh @ Wo
__device__ float  g_SEG[(size_t)BN * 16 * DN];

// ---------------- helpers ----------------
__device__ __forceinline__ uint32_t smem_u32(const void* p) {
    uint32_t a;
    asm("{ .reg .u64 t; cvta.to.shared.u64 t, %1; cvt.u32.u64 %0, t; }" : "=r"(a) : "l"(p));
    return a;
}
__device__ __forceinline__ float ex2f(float x) {
    float y;
    asm("ex2.approx.ftz.f32 %0, %1;" : "=f"(y) : "f"(x));
    return y;
}
__device__ __forceinline__ void cp_async16(uint32_t dst, const void* src) {
    asm volatile("cp.async.cg.shared.global [%0], [%1], 16;" :: "r"(dst), "l"(src));
}
__device__ __forceinline__ void cp_commit() { asm volatile("cp.async.commit_group;"); }
__device__ __forceinline__ void cp_wait0()  { asm volatile("cp.async.wait_group 0;"); }
__device__ __forceinline__ void cp_wait1()  { asm volatile("cp.async.wait_group 1;"); }
__device__ __forceinline__ uint32_t swz(uint32_t off) {
    return off ^ ((off >> 3) & 0x70);
}
__device__ __forceinline__ void ldsm4(uint32_t& r0, uint32_t& r1, uint32_t& r2, uint32_t& r3,
                                      uint32_t addr) {
    asm volatile("ldmatrix.sync.aligned.m8n8.x4.shared.b16 {%0,%1,%2,%3}, [%4];"
        : "=r"(r0), "=r"(r1), "=r"(r2), "=r"(r3) : "r"(addr));
}
__device__ __forceinline__ void ldsm4t(uint32_t& r0, uint32_t& r1, uint32_t& r2, uint32_t& r3,
                                       uint32_t addr) {
    asm volatile("ldmatrix.sync.aligned.m8n8.x4.trans.shared.b16 {%0,%1,%2,%3}, [%4];"
        : "=r"(r0), "=r"(r1), "=r"(r2), "=r"(r3) : "r"(addr));
}
__device__ __forceinline__ void mma_16816(float* c, const uint32_t* a, const uint32_t* b) {
    asm volatile("mma.sync.aligned.m16n8k16.row.col.f32.f16.f16.f32 "
        "{%0,%1,%2,%3},{%4,%5,%6,%7},{%8,%9},{%0,%1,%2,%3};"
        : "+f"(c[0]), "+f"(c[1]), "+f"(c[2]), "+f"(c[3])
        : "r"(a[0]), "r"(a[1]), "r"(a[2]), "r"(a[3]), "r"(b[0]), "r"(b[1]));
}

// ================= GEMM core (128x128 CTA tile, 3-stage, 2 CTA/SM) =================
constexpr int GM_STAGE = 32768;            // A 16KB + B 16KB
constexpr int GM_SMEM  = 3 * GM_STAGE;     // 96KB

template<typename EpiFn>
__device__ __forceinline__ void gemm_body(
    const __half* __restrict__ A, const __half* __restrict__ Bm,
    int K, int lda, int ldb, uint32_t sb, EpiFn epi)
{
    const int tid = threadIdx.x, wid = tid >> 5, lane = tid & 31;
    const int wm = wid >> 2, wn = wid & 3;           // 2x4 warp grid
    const int m0 = blockIdx.y * 128, n0 = blockIdx.x * 128;

    float acc[64];
#pragma unroll
    for (int i = 0; i < 64; i++) acc[i] = 0.f;

    const int CC = K >> 6;   // 64-half chunks

    auto load_chunk = [&](int st, int c) {
        int k0 = c << 6;
        const uint32_t sa = sb + st * GM_STAGE;
#pragma unroll
        for (int i = 0; i < 4; i++) {
            int u = tid + i * 256;
            int r = u >> 3, ku = u & 7;
            cp_async16(sa + swz(r * 128 + ku * 16),
                       A + (size_t)(m0 + r) * lda + k0 + ku * 8);
        }
#pragma unroll
        for (int i = 0; i < 4; i++) {
            int u = tid + i * 256;
            int r = u >> 3, ku = u & 7;
            cp_async16(sa + 16384 + swz(r * 128 + ku * 16),
                       Bm + (size_t)(n0 + r) * ldb + k0 + ku * 8);
        }
        cp_commit();
    };

    const int row16 = lane & 15;
    const int aKh   = (lane >> 4) & 1;
    uint32_t aBase[4], aSx[4];
#pragma unroll
    for (int mt = 0; mt < 4; mt++) {
        int m = wm * 64 + mt * 16 + row16;
        aBase[mt] = m * 128;
        aSx[mt] = (m & 7) << 4;
    }
    const int bKh   = (lane >> 3) & 1;
    const int bN8   = (lane >> 4) & 1;
    uint32_t bBase[2], bSx[2];
#pragma unroll
    for (int p = 0; p < 2; p++) {
        int n = wn * 32 + p * 16 + bN8 * 8 + (lane & 7);
        bBase[p] = 16384 + n * 128;
        bSx[p] = (n & 7) << 4;
    }

    load_chunk(0, 0);
    load_chunk(1, 1);
    int st = 0;
    for (int c = 0; c < CC; c++) {
        if (c < CC - 1) cp_wait1(); else cp_wait0();
        __syncthreads();
        if (c + 2 < CC) {
            int st2 = st + 2; if (st2 >= 3) st2 -= 3;
            load_chunk(st2, c + 2);
        }
        const uint32_t buf = sb + st * GM_STAGE;
#pragma unroll
        for (int kk = 0; kk < 4; kk++) {
            uint32_t a[4][4];
            const uint32_t kofA = ((uint32_t)(kk << 5)) | (aKh << 4);
#pragma unroll
            for (int mt = 0; mt < 4; mt++)
                ldsm4(a[mt][0], a[mt][1], a[mt][2], a[mt][3],
                      buf + aBase[mt] + (kofA ^ aSx[mt]));
            uint32_t b[4][2];
            const uint32_t kofB = ((uint32_t)(kk << 5)) | (bKh << 4);
#pragma unroll
            for (int p = 0; p < 2; p++) {
                uint32_t r0, r1, r2, r3;
                ldsm4(r0, r1, r2, r3, buf + bBase[p] + (kofB ^ bSx[p]));
                b[p * 2 + 0][0] = r0; b[p * 2 + 0][1] = r1;
                b[p * 2 + 1][0] = r2; b[p * 2 + 1][1] = r3;
            }
#pragma unroll
            for (int mt = 0; mt < 4; mt++)
#pragma unroll
                for (int nt = 0; nt < 4; nt++)
                    mma_16816(&acc[(mt * 4 + nt) * 4], a[mt], b[nt]);
        }
        if (++st >= 3) st = 0;
    }

    const int gid = lane >> 2, tig = lane & 3;
#pragma unroll
    for (int mt = 0; mt < 4; mt++) {
        int m = m0 + wm * 64 + mt * 16 + gid;
#pragma unroll
        for (int nt = 0; nt < 4; nt++) {
            int n = n0 + wn * 32 + nt * 8 + 2 * tig;
            const float* cc = &acc[(mt * 4 + nt) * 4];
            epi(m,     n, cc[0], cc[1]);
            epi(m + 8, n, cc[2], cc[3]);
        }
    }
}

// ---- fused Q/K/V projection: grid.z selects input/weight/bias ----
__global__ void __launch_bounds__(256, 2)
hgemm_qkv(const __half* __restrict__ qkv, const __half* __restrict__ Wt,
          const float* __restrict__ bq, const float* __restrict__ bk,
          const float* __restrict__ bv,
          __half* __restrict__ Qh, __half* __restrict__ Kh,
          __half* __restrict__ Vh)
{
    extern __shared__ char smem[];
    const uint32_t sb = smem_u32(smem);
    const int z = blockIdx.z;
    const __half* A = qkv + (size_t)z * MR * DN;
    const __half* B = Wt  + (size_t)z * DN * DN;
    const float* bias = (z == 0) ? bq : (z == 1) ? bk : bv;
    const float scale = (z == 0) ? QK_SCALE * LOG2E : 1.f;   // Q carries log2e
    __half* Ch = (z == 0) ? Qh : (z == 1) ? Kh : Vh;

    gemm_body(A, B, DN, DN, DN, sb, [&](int m, int n, float x, float y) {
        float2 bb = *(const float2*)(bias + n);
        float vx = (x + bb.x) * scale, vy = (y + bb.y) * scale;
        int bi = m >> 11, s = m & 2047;
        int h = n >> 7, dh = n & 127;
        size_t hb = (size_t)(bi * HN + h);
        *(__half2*)(Ch + (hb * SN + s) * DHN + dh) = __floats2half2_rn(vx, vy);
    });
}

// ---- SUF = SVh @ Wo (fp32 out) ----
__global__ void __launch_bounds__(256, 2)
hgemm_suf(const __half* __restrict__ A, const __half* __restrict__ Bm,
          float* __restrict__ C)
{
    extern __shared__ char smem[];
    const uint32_t sb = smem_u32(smem);
    gemm_body(A, Bm, DN, DN, DN, sb, [&](int m, int n, float x, float y) {
        *(float2*)(C + (size_t)m * DN + n) = make_float2(x, y);
    });
}

// ---- out = PVm @ Wo + bo - 1e9*SUF (fp32 out) ----
__global__ void __launch_bounds__(256, 2)
hgemm_out(const __half* __restrict__ A, const __half* __restrict__ Bm,
          const float* __restrict__ bias, const float* __restrict__ suf,
          float* __restrict__ C)
{
    extern __shared__ char smem[];
    const uint32_t sb = smem_u32(smem);
    gemm_body(A, Bm, DN, DN, DN, sb, [&](int m, int n, float x, float y) {
        float2 bb = *(const float2*)(bias + n);
        const float* sf = suf + (size_t)m * DN + n;
        *(float2*)(C + (size_t)m * DN + n) =
            make_float2(x + bb.x - 1e9f * sf[0], y + bb.y - 1e9f * sf[1]);
    });
}

// ---------------- flash attention (2-stage, 96KB, 2 CTA/SM) ----------------
// grid (qt=16, bh=64). 8 warps x 16 q-rows. Bc=64 kv/iter, 32 iters.
// smem: Q 32K, K 2x16K, V 2x16K = 96KB. exp2 domain (Q pre-scaled).
// V stored [kv, dh] like K; PV B-fragments via ldmatrix.trans.
constexpr int FL_SMEM = 32768 + 4 * 16384;

__global__ void __launch_bounds__(256, 2)
flash_attn(const __half* __restrict__ Qg, const __half* __restrict__ Kg,
           const __half* __restrict__ Vg, __half* __restrict__ PVm)
{
    extern __shared__ char smem[];
    const uint32_t sb = smem_u32(smem);
    constexpr uint32_t QS = 0, KS = 32768, VS = 32768 + 2 * 16384;
    const int tid = threadIdx.x, wid = tid >> 5, lane = tid & 31;
    const int qt = blockIdx.x, bh = blockIdx.y;
    const int b = bh >> 4, h = bh & 15;
    const __half* Qp = Qg + (size_t)bh * SN * DHN;
    const __half* Kp = Kg + (size_t)bh * SN * DHN;
    const __half* Vp = Vg + (size_t)bh * SN * DHN;
    const int vlast = 2 * qt + 1;      // last kv tile needed for PV

    // Q tile: 128 rows x 128 dh (2 subtiles of 64 dh)
#pragma unroll
    for (int i = 0; i < 8; i++) {
        int u = tid + i * 256;
        int r = u >> 4, ku = u & 15;
        cp_async16(sb + QS + (ku >> 3) * 16384 + swz(r * 128 + (ku & 7) * 16),
                   Qp + (size_t)(qt * 128 + r) * DHN + ku * 8);
    }
    auto loadKV = [&](int kt, int stg) {
#pragma unroll
        for (int i = 0; i < 4; i++) {
            int u = tid + i * 256;
            int r = u >> 4, ku = u & 15;
            cp_async16(sb + KS + stg * 16384 + (ku >> 3) * 8192 + swz(r * 128 + (ku & 7) * 16),
                       Kp + (size_t)(kt * 64 + r) * DHN + ku * 8);
        }
        if (kt <= vlast) {
#pragma unroll
            for (int i = 0; i < 4; i++) {
                int u = tid + i * 256;
                int r = u >> 4, ku = u & 15;
                cp_async16(sb + VS + stg * 16384 + (ku >> 3) * 8192 + swz(r * 128 + (ku & 7) * 16),
                           Vp + (size_t)(kt * 64 + r) * DHN + ku * 8);
            }
        }
        cp_commit();
    };
    loadKV(0, 0);

    const int gid = lane >> 2, tig = lane & 3;
    const int am = wid * 16 + (lane & 15);
    const int aKh = (lane >> 4) & 1;
    const uint32_t aBase = am * 128, aSx = (am & 7) << 4;
    const int bKh = (lane >> 3) & 1, bN8 = (lane >> 4) & 1;
    const uint32_t laneSwz = (uint32_t)(lane & 7) << 4;
    const int kvLane = bKh * 8 + (lane & 7);

    const int q0 = qt * 128 + wid * 16 + gid;
    const int q1 = q0 + 8;
    const int qmaxw = qt * 128 + wid * 16 + 15;

    float m0r = -1e30f, m1r = -1e30f, l0 = 0.f, l1 = 0.f;
    float oacc[16][4];
#pragma unroll
    for (int i = 0; i < 16; i++)
#pragma unroll
        for (int j = 0; j < 4; j++) oacc[i][j] = 0.f;

    for (int kt = 0; kt < 32; kt++) {
        const int stg = kt & 1;
        if (kt + 1 < 32) { loadKV(kt + 1, stg ^ 1); cp_wait1(); }
        else             { cp_wait0(); }
        __syncthreads();

        // S = Q @ K^T  (16 x 64 per warp), log2-domain scores
        float sacc[8][4];
#pragma unroll
        for (int nt = 0; nt < 8; nt++)
#pragma unroll
            for (int j = 0; j < 4; j++) sacc[nt][j] = 0.f;
#pragma unroll
        for (int kk = 0; kk < 8; kk++) {
            uint32_t a[4];
            const uint32_t kofA = ((uint32_t)((kk & 3) << 5)) | (aKh << 4);
            ldsm4(a[0], a[1], a[2], a[3],
                  sb + QS + (kk >> 2) * 16384 + aBase + (kofA ^ aSx));
            const uint32_t kofB = ((uint32_t)((kk & 3) << 5)) | (bKh << 4);
            const uint32_t kb = sb + KS + stg * 16384 + (kk >> 2) * 8192;
#pragma unroll
            for (int p = 0; p < 4; p++) {
                int n = p * 16 + bN8 * 8 + (lane & 7);
                uint32_t r0, r1, r2, r3;
                ldsm4(r0, r1, r2, r3, kb + n * 128 + (kofB ^ ((n & 7) << 4)));
                uint32_t b0[2] = {r0, r1}, b1[2] = {r2, r3};
                mma_16816(sacc[p * 2 + 0], a, b0);
                mma_16816(sacc[p * 2 + 1], a, b1);
            }
        }

        // online softmax (full row, exp2 domain)
        float mx0 = -1e30f, mx1 = -1e30f;
#pragma unroll
        for (int nt = 0; nt < 8; nt++) {
            mx0 = fmaxf(mx0, fmaxf(sacc[nt][0], sacc[nt][1]));
            mx1 = fmaxf(mx1, fmaxf(sacc[nt][2], sacc[nt][3]));
        }
        mx0 = fmaxf(mx0, __shfl_xor_sync(0xffffffffu, mx0, 1));
        mx0 = fmaxf(mx0, __shfl_xor_sync(0xffffffffu, mx0, 2));
        mx1 = fmaxf(mx1, __shfl_xor_sync(0xffffffffu, mx1, 1));
        mx1 = fmaxf(mx1, __shfl_xor_sync(0xffffffffu, mx1, 2));
        float mn0 = fmaxf(m0r, mx0), mn1 = fmaxf(m1r, mx1);
        float sc0 = ex2f(m0r - mn0), sc1 = ex2f(m1r - mn1);
        m0r = mn0; m1r = mn1;
        if (__ballot_sync(0xffffffffu, (sc0 != 1.f) | (sc1 != 1.f))) {
            l0 *= sc0; l1 *= sc1;
#pragma unroll
            for (int nt = 0; nt < 16; nt++) {
                oacc[nt][0] *= sc0; oacc[nt][1] *= sc0;
                oacc[nt][2] *= sc1; oacc[nt][3] *= sc1;
            }
        }
        const int kvb = kt * 64;
        uint32_t pf[8][2];
#pragma unroll
        for (int nt = 0; nt < 8; nt++) {
            int c0 = kvb + nt * 8 + 2 * tig, c1 = c0 + 1;
            float e0 = ex2f(sacc[nt][0] - mn0), e1 = ex2f(sacc[nt][1] - mn0);
            float e2 = ex2f(sacc[nt][2] - mn1), e3 = ex2f(sacc[nt][3] - mn1);
            l0 += e0 + e1; l1 += e2 + e3;
            __half2 h01 = __floats2half2_rn(c0 <= q0 ? e0 : 0.f, c1 <= q0 ? e1 : 0.f);
            __half2 h23 = __floats2half2_rn(c0 <= q1 ? e2 : 0.f, c1 <= q1 ? e3 : 0.f);
            pf[nt][0] = *(uint32_t*)&h01;
            pf[nt][1] = *(uint32_t*)&h23;
        }

        // PV accumulate via ldmatrix.trans on [kv,dh] V tile
        if (kvb <= qmaxw) {
            const uint32_t vb = sb + VS + stg * 16384;
#pragma unroll
            for (int j = 0; j < 4; j++) {
                uint32_t a2[4] = { pf[2 * j][0], pf[2 * j][1], pf[2 * j + 1][0], pf[2 * j + 1][1] };
                const uint32_t rowoff = (uint32_t)(j * 16 + kvLane) * 128;
#pragma unroll
                for (int p = 0; p < 8; p++) {
                    int dhseg = p * 16 + bN8 * 8;
                    uint32_t addr = vb + ((dhseg >> 6) * 8192) + rowoff
                                    + (((uint32_t)(dhseg & 63) * 2) ^ laneSwz);
                    uint32_t r0, r1, r2, r3;
                    ldsm4t(r0, r1, r2, r3, addr);
                    uint32_t b0[2] = {r0, r1}, b1[2] = {r2, r3};
                    mma_16816(oacc[p * 2 + 0], a2, b0);
                    mma_16816(oacc[p * 2 + 1], a2, b1);
                }
            }
        }
        __syncthreads();   // protect the buffer loaded next iter
    }

    // finalize
    l0 += __shfl_xor_sync(0xffffffffu, l0, 1);
    l0 += __shfl_xor_sync(0xffffffffu, l0, 2);
    l1 += __shfl_xor_sync(0xffffffffu, l1, 1);
    l1 += __shfl_xor_sync(0xffffffffu, l1, 2);
    const float i0 = 1.f / l0, i1 = 1.f / l1;
#pragma unroll
    for (int nt = 0; nt < 16; nt++) {
        int dh = nt * 8 + 2 * tig;
        __half2 ha = __floats2half2_rn(oacc[nt][0] * i0, oacc[nt][1] * i0);
        __half2 hb = __floats2half2_rn(oacc[nt][2] * i1, oacc[nt][3] * i1);
        *(__half2*)(PVm + ((size_t)(b * SN) + q0) * DN + h * 128 + dh) = ha;
        *(__half2*)(PVm + ((size_t)(b * SN) + q1) * DN + h * 128 + dh) = hb;
    }
}

// ---------------- fused prepass: fp32->fp16 converts + weight transposes ----------------
__global__ void __launch_bounds__(256)
prepass(const float* __restrict__ q, const float* __restrict__ k,
        const float* __restrict__ v,
        const float* __restrict__ W0, const float* __restrict__ W1,
        const float* __restrict__ W2, const float* __restrict__ W3,
        __half* __restrict__ qkvh, __half* __restrict__ Wt)
{
    __shared__ float t[32][33];
    if (blockIdx.y < 3) {
        const float* x = (blockIdx.y == 0) ? q : (blockIdx.y == 1) ? k : v;
        size_t i = (size_t)blockIdx.x * 256 + threadIdx.x;
        float4 vv = ((const float4*)x)[i];
        __half2 h0 = __floats2half2_rn(vv.x, vv.y);
        __half2 h1 = __floats2half2_rn(vv.z, vv.w);
        ((uint2*)(qkvh + (size_t)blockIdx.y * MR * DN))[i] =
            make_uint2(*(uint32_t*)&h0, *(uint32_t*)&h1);
        return;
    }
    int u = blockIdx.x;              // 0..16383 = 4 weights x 64 x 64 tiles
    int w = u >> 12, rem = u & 4095;
    int k0 = (rem >> 6) * 32, n0 = (rem & 63) * 32;
    const float* W = (w == 0) ? W0 : (w == 1) ? W1 : (w == 2) ? W2 : W3;
    __half* Wo = Wt + (size_t)w * DN * DN;
    int tx = threadIdx.x & 31, ty = threadIdx.x >> 5;
#pragma unroll
    for (int j = ty; j < 32; j += 8)
        t[j][tx] = W[(size_t)(k0 + j) * DN + n0 + tx];
    __syncthreads();
#pragma unroll
    for (int j = ty; j < 32; j += 8)
        Wo[(size_t)(n0 + j) * DN + k0 + tx] = __float2half_rn(t[tx][j]);
}

// ---------------- suffix sums of V-proj (head layout in, merged fp16 out) ----------------
__global__ void __launch_bounds__(256)
suf_pass1(const __half* __restrict__ Vh, float* __restrict__ seg)
{
    int b = blockIdx.x, sg = blockIdx.y;
    int d = blockIdx.z * 256 + threadIdx.x;
    int h = d >> 7, dh = d & 127;
    const __half* u = Vh + (((size_t)(b * HN + h) * SN) + sg * 128) * DHN + dh;
    float a = 0.f;
#pragma unroll 8
    for (int i = 0; i < 128; i++) a += __half2float(u[(size_t)i * DHN]);
    seg[((size_t)b * 16 + sg) * DN + d] = a;
}

__global__ void __launch_bounds__(256)
suf_pass2(const __half* __restrict__ Vh, const float* __restrict__ seg,
          __half* __restrict__ SVh)
{
    int b = blockIdx.x, sg = blockIdx.y;
    int d = blockIdx.z * 256 + threadIdx.x;
    int h = d >> 7, dh = d & 127;
    float off = 0.f;
    for (int j = sg + 1; j < 16; j++) off += seg[((size_t)b * 16 + j) * DN + d];
    const __half* u = Vh + (((size_t)(b * HN + h) * SN) + sg * 128) * DHN + dh;
    __half* o = SVh + ((size_t)b * SN + sg * 128) * DN + d;
    float a = off;
    for (int i = 127; i >= 0; i--) {
        o[(size_t)i * DN] = __float2half_rn(a);
        a += __half2float(u[(size_t)i * DHN]);
    }
}

// ---------------- launch ----------------
extern "C" void kernel_launch(void* const* d_in, const int* in_sizes, int n_in,
                              void* d_out, int out_size)
{
    const float* q  = (const float*)d_in[0];
    const float* k  = (const float*)d_in[1];
    const float* v  = (const float*)d_in[2];
    const float* Wq = (const float*)d_in[3];
    const float* bq = (const float*)d_in[4];
    const float* Wk = (const float*)d_in[5];
    const float* bk = (const float*)d_in[6];
    const float* Wv = (const float*)d_in[7];
    const float* bv = (const float*)d_in[8];
    const float* Wo = (const float*)d_in[9];
    const float* bo = (const float*)d_in[10];
    float* out = (float*)d_out;

    void *p;
    __half *qkvh, *Wt, *Qh, *Kh, *Vh, *SVh, *PVm;
    float *SUF, *SEG;
    cudaGetSymbolAddress(&p, g_qkvh); qkvh = (__half*)p;
    cudaGetSymbolAddress(&p, g_Wt);   Wt   = (__half*)p;
    cudaGetSymbolAddress(&p, g_Q);    Qh   = (__half*)p;
    cudaGetSymbolAddress(&p, g_K);    Kh   = (__half*)p;
    cudaGetSymbolAddress(&p, g_Vh);   Vh   = (__half*)p;
    cudaGetSymbolAddress(&p, g_SVh);  SVh  = (__half*)p;
    cudaGetSymbolAddress(&p, g_PVm);  PVm  = (__half*)p;
    cudaGetSymbolAddress(&p, g_SUF);  SUF  = (float*)p;
    cudaGetSymbolAddress(&p, g_SEG);  SEG  = (float*)p;
    __half* Wto = Wt + 3 * (size_t)DN * DN;

    cudaFuncSetAttribute(hgemm_qkv, cudaFuncAttributeMaxDynamicSharedMemorySize, GM_SMEM);
    cudaFuncSetAttribute(hgemm_suf, cudaFuncAttributeMaxDynamicSharedMemorySize, GM_SMEM);
    cudaFuncSetAttribute(hgemm_out, cudaFuncAttributeMaxDynamicSharedMemorySize, GM_SMEM);
    cudaFuncSetAttribute(flash_attn, cudaFuncAttributeMaxDynamicSharedMemorySize, FL_SMEM);

    // One-time side stream + events (host objects only; no device allocation).
    static cudaStream_t s1 = nullptr;
    static cudaEvent_t  e1 = nullptr, e2 = nullptr;
    if (s1 == nullptr) {
        cudaStreamCreateWithFlags(&s1, cudaStreamNonBlocking);
        cudaEventCreateWithFlags(&e1, cudaEventDisableTiming);
        cudaEventCreateWithFlags(&e2, cudaEventDisableTiming);
    }

    // 0) fused prepass: convert q/k/v to fp16 + transpose/convert weights
    dim3 gP(16384, 4);
    prepass<<<gP, 256>>>(q, k, v, Wq, Wk, Wv, Wo, qkvh, Wt);

    // 1) fused Q/K/V projections (Q pre-scaled by log2e/sqrt(DH))
    dim3 gProj(DN / 128, MR / 128, 3);   // (16, 64, 3)
    hgemm_qkv<<<gProj, 256, GM_SMEM>>>(qkvh, Wt, bq, bk, bv, Qh, Kh, Vh);

    // fork: suffix branch on s1 (needs only Vh), concurrent with flash (main)
    cudaEventRecord(e1, 0);
    cudaStreamWaitEvent(s1, e1, 0);
    dim3 gSuf(BN, 16, DN / 256);
    suf_pass1<<<gSuf, 256, 0, s1>>>(Vh, SEG);
    suf_pass2<<<gSuf, 256, 0, s1>>>(Vh, SEG, SVh);
    dim3 gU(DN / 128, MR / 128);
    hgemm_suf<<<gU, 256, GM_SMEM, s1>>>(SVh, Wto, SUF);
    cudaEventRecord(e2, s1);

    // 2) flash attention -> merged PV [B,S,D] fp16 (main stream, overlaps s1)
    dim3 gFl(16, 64);
    flash_attn<<<gFl, 256, FL_SMEM>>>(Qh, Kh, Vh, PVm);

    // join, then 3) out = PVm @ Wo + bo - 1e9 * SUF
    cudaStreamWaitEvent(0, e2, 0);
    hgemm_out<<<gU, 256, GM_SMEM>>>(PVm, Wto, bo, SUF, out);
}